// round 2
// baseline (speedup 1.0000x reference)
#include <cuda_runtime.h>
#include <math.h>

// ---------------------------------------------------------------------------
// RGCN CSR layer, fused:  agg (gather+add over edges, per 64-node tile, SMEM)
//                          -> GEMM [64 x 512] x [512 x F_OUT] (W staged in SMEM)
//                          -> epilogue (ReLU -> scratch | log_softmax -> out)
// Layer algebra: h[i,f] = sum_e x[src_e] @ W[rel_e]  (edges of row i)
//              = sum_k agg[i,k] * Wflat[k,f],  k = rel*64 + d
// ---------------------------------------------------------------------------

#define MAXN 75000

__device__ float g_h[MAXN * 64];   // layer-1 output (post-ReLU) scratch, 19.2 MB

template<int F_OUT, bool FIRST>
__global__ void __launch_bounds__(256, 1)
rgcn_layer_kernel(const float* __restrict__ x,
                  const int*   __restrict__ ptr,
                  const int*   __restrict__ idx,
                  const int*   __restrict__ rel,
                  const float* __restrict__ W,     // [512][F_OUT] flattened
                  float*       __restrict__ out,   // used only when !FIRST
                  int n_nodes)
{
    constexpr int D    = 64;        // per-relation feature dim (both layers)
    constexpr int KTOT = 512;       // R * D
    constexpr int TN   = 64;        // nodes per block
    constexpr int AST  = KTOT + 4;  // agg row stride (516: 16B-aligned rows, bank shift)
    constexpr int KC   = 256;       // K-chunk of W staged in SMEM

    extern __shared__ float smem[];
    float* agg  = smem;                 // [TN][AST]
    float* wbuf = smem + TN * AST;      // [KC][F_OUT]

    const int tid   = threadIdx.x;
    const int lane  = tid & 31;
    const int warp  = tid >> 5;
    const int node0 = blockIdx.x * TN;

    const float* xin = FIRST ? x : (const float*)g_h;
    float*       dst = FIRST ? (float*)g_h : out;

    // ---- zero agg tile -----------------------------------------------------
    {
        float4 z = make_float4(0.f, 0.f, 0.f, 0.f);
        float4* p = (float4*)agg;
        #pragma unroll 4
        for (int i = tid; i < TN * AST / 4; i += 256) p[i] = z;
    }
    __syncthreads();

    // ---- edge aggregation: one warp per node, lanes = 2 features each ------
    for (int n = warp; n < TN; n += 8) {
        int g = node0 + n;
        if (g >= n_nodes) break;
        int e0 = ptr[g], e1 = ptr[g + 1];
        float* arow = agg + n * AST;
        for (int eb = e0; eb < e1; eb += 32) {
            int cnt = min(32, e1 - eb);
            int mi = 0, mr = 0;
            if (lane < cnt) { mi = idx[eb + lane]; mr = rel[eb + lane]; }
            for (int t = 0; t < cnt; ++t) {
                int s = __shfl_sync(0xffffffffu, mi, t);
                int r = __shfl_sync(0xffffffffu, mr, t);
                float2 v = ((const float2*)(xin + (size_t)s * D))[lane];
                float2* a = ((float2*)(arow + r * D)) + lane;
                float2 c = *a;
                c.x += v.x; c.y += v.y;
                *a = c;
            }
        }
    }
    __syncthreads();

    // ---- GEMM: out_tile[64][F_OUT] = agg[64][512] @ W[512][F_OUT] ----------
    constexpr int CT = (F_OUT + 3) / 4;      // active column groups of 4
    const int tx = tid & 15;                 // col group
    const int ty = tid >> 4;                 // row group (4 rows each)
    const bool active = (tx < CT);
    float acc[4][4] = {};

    for (int kk = 0; kk < KTOT; kk += KC) {
        // stage W chunk [KC][F_OUT] into SMEM (contiguous in global)
        {
            const float4* Wg  = (const float4*)(W + (size_t)kk * F_OUT);
            float4*       wb4 = (float4*)wbuf;
            #pragma unroll 4
            for (int i = tid; i < KC * F_OUT / 4; i += 256) wb4[i] = Wg[i];
        }
        __syncthreads();

        if (active) {
            const float* abase = agg  + (ty * 4) * AST + kk;
            const float* bbase = wbuf + tx * 4;
            #pragma unroll 2
            for (int k = 0; k < KC; k += 4) {
                float4 b0 = *(const float4*)(bbase + (k + 0) * F_OUT);
                float4 b1 = *(const float4*)(bbase + (k + 1) * F_OUT);
                float4 b2 = *(const float4*)(bbase + (k + 2) * F_OUT);
                float4 b3 = *(const float4*)(bbase + (k + 3) * F_OUT);
                #pragma unroll
                for (int j = 0; j < 4; ++j) {
                    float4 a = *(const float4*)(abase + j * AST + k);
                    acc[j][0] += a.x * b0.x + a.y * b1.x + a.z * b2.x + a.w * b3.x;
                    acc[j][1] += a.x * b0.y + a.y * b1.y + a.z * b2.y + a.w * b3.y;
                    acc[j][2] += a.x * b0.z + a.y * b1.z + a.z * b2.z + a.w * b3.z;
                    acc[j][3] += a.x * b0.w + a.y * b1.w + a.z * b2.w + a.w * b3.w;
                }
            }
        }
        __syncthreads();
    }

    if (FIRST) {
        // ---- ReLU, store to scratch --------------------------------------
        if (active) {
            #pragma unroll
            for (int j = 0; j < 4; ++j) {
                int g = node0 + ty * 4 + j;
                if (g < n_nodes) {
                    float4 v;
                    v.x = fmaxf(acc[j][0], 0.f);
                    v.y = fmaxf(acc[j][1], 0.f);
                    v.z = fmaxf(acc[j][2], 0.f);
                    v.w = fmaxf(acc[j][3], 0.f);
                    *(float4*)(dst + (size_t)g * F_OUT + tx * 4) = v;
                }
            }
        }
    } else {
        // ---- log_softmax over F_OUT, store final output -------------------
        constexpr int OST = F_OUT + 8;       // padded row stride in SMEM
        float* ot = smem;                    // reuse agg region (synced above)
        if (active) {
            #pragma unroll
            for (int j = 0; j < 4; ++j) {
                float* row = ot + (ty * 4 + j) * OST + tx * 4;
                row[0] = acc[j][0];
                row[1] = acc[j][1];
                row[2] = acc[j][2];
                row[3] = acc[j][3];
            }
        }
        __syncthreads();
        for (int n = warp; n < TN; n += 8) {
            int g = node0 + n;
            if (g >= n_nodes) break;
            const float* row = ot + n * OST;
            float v1 = (lane < F_OUT)      ? row[lane]      : -INFINITY;
            float v2 = (lane + 32 < F_OUT) ? row[lane + 32] : -INFINITY;
            float m = fmaxf(v1, v2);
            #pragma unroll
            for (int o = 16; o; o >>= 1)
                m = fmaxf(m, __shfl_xor_sync(0xffffffffu, m, o));
            float s = ((lane < F_OUT)      ? expf(v1 - m) : 0.f)
                    + ((lane + 32 < F_OUT) ? expf(v2 - m) : 0.f);
            #pragma unroll
            for (int o = 16; o; o >>= 1)
                s += __shfl_xor_sync(0xffffffffu, s, o);
            float lse = m + logf(s);
            if (lane < F_OUT)      dst[(size_t)g * F_OUT + lane]      = v1 - lse;
            if (lane + 32 < F_OUT) dst[(size_t)g * F_OUT + lane + 32] = v2 - lse;
        }
    }
}

extern "C" void kernel_launch(void* const* d_in, const int* in_sizes, int n_in,
                              void* d_out, int out_size)
{
    const float* x   = (const float*)d_in[0];
    const int*   ptr = (const int*)  d_in[1];
    const int*   idx = (const int*)  d_in[2];
    const int*   rel = (const int*)  d_in[3];
    const float* W1  = (const float*)d_in[4];   // [8][64][64] -> [512][64]
    const float* W2  = (const float*)d_in[5];   // [8][64][40] -> [512][40]
    float* out = (float*)d_out;

    int n    = in_sizes[1] - 1;                 // ptr has N+1 entries
    int grid = (n + 63) / 64;

    const int s1 = (64 * 516 + 256 * 64) * (int)sizeof(float);  // 197632 B
    const int s2 = (64 * 516 + 256 * 40) * (int)sizeof(float);  // 173056 B
    cudaFuncSetAttribute(rgcn_layer_kernel<64, true>,
                         cudaFuncAttributeMaxDynamicSharedMemorySize, s1);
    cudaFuncSetAttribute(rgcn_layer_kernel<40, false>,
                         cudaFuncAttributeMaxDynamicSharedMemorySize, s2);

    rgcn_layer_kernel<64, true ><<<grid, 256, s1>>>(x, ptr, idx, rel, W1, out, n);
    rgcn_layer_kernel<40, false><<<grid, 256, s2>>>(x, ptr, idx, rel, W2, out, n);
}

// round 3
// speedup vs baseline: 1.0539x; 1.0539x over previous
#include <cuda_runtime.h>
#include <math.h>

// ---------------------------------------------------------------------------
// RGCN fused layer: register aggregation -> transposed agg in SMEM ->
// K-split FFMA2 (f32x2) GEMM with full W resident in SMEM -> epilogue.
//   h[i,f] = sum_k agg[i,k] * Wflat[k,f],  k = rel*64 + d
// Block: 32 nodes, 512 threads (16 warps). K-split 8 (64 k per slice).
// Thread GEMM tile: 4 rows x (F/8) cols, f32x2 packed over column pairs.
// ---------------------------------------------------------------------------

#define MAXN 75000
__device__ float g_h[MAXN * 64];   // layer-1 output (post-ReLU), 19.2 MB

typedef unsigned long long ull;

__device__ __forceinline__ ull pk2(float x, float y) {
    ull r; asm("mov.b64 %0, {%1, %2};" : "=l"(r) : "f"(x), "f"(y)); return r;
}
__device__ __forceinline__ void upk2(ull v, float& x, float& y) {
    asm("mov.b64 {%0, %1}, %2;" : "=f"(x), "=f"(y) : "l"(v));
}
__device__ __forceinline__ void ffma2(ull& d, ull a, ull b) {
    asm("fma.rn.f32x2 %0, %1, %2, %0;" : "+l"(d) : "l"(a), "l"(b));
}

template<int F_OUT, bool FIRST>
__global__ void __launch_bounds__(512, 1)
rgcn_layer_kernel(const float* __restrict__ x,
                  const int*   __restrict__ ptr,
                  const int*   __restrict__ idx,
                  const int*   __restrict__ rel,
                  const float* __restrict__ W,     // [512][F_OUT]
                  float*       __restrict__ out,
                  int n_nodes)
{
    constexpr int KTOT = 512;
    constexpr int TN   = 32;             // nodes per block
    constexpr int TNS  = 34;             // aggT row stride (pad)
    constexpr int CPG  = F_OUT / 8;      // cols per col-group (8 or 5)
    constexpr int CPAIR = CPG / 2;       // f32x2 col pairs (4 or 2)
    constexpr bool SCL = (CPG & 1);      // odd trailing column (layer2)
    constexpr int AGGF = KTOT * TNS;     // floats in aggT region

    extern __shared__ float smem[];
    float* aggT = smem;                  // [512][TNS] transposed agg
    float* wbuf = smem + AGGF;           // [512][F_OUT]

    const int tid  = threadIdx.x;
    const int lane = tid & 31;
    const int warp = tid >> 5;
    const int node0 = blockIdx.x * TN;

    const float* xin = FIRST ? x : (const float*)g_h;

    // ---- stage full W into SMEM (contiguous float4 copy) --------------------
    {
        const float4* Wg = (const float4*)W;
        float4* wb = (float4*)wbuf;
        constexpr int NV = KTOT * F_OUT / 4;
        #pragma unroll 4
        for (int i = tid; i < NV; i += 512) wb[i] = Wg[i];
    }

    // ---- aggregation: warp per node (2 nodes/warp), register accumulation ---
    for (int nl = warp; nl < TN; nl += 16) {
        int g = node0 + nl;
        if (g < n_nodes) {
            float2 acc[8];
            #pragma unroll
            for (int r = 0; r < 8; ++r) acc[r] = make_float2(0.f, 0.f);

            int e0 = ptr[g], e1 = ptr[g + 1];
            for (int eb = e0; eb < e1; eb += 32) {
                int cend = min(32, e1 - eb);
                int mi = 0, mr = 0;
                if (lane < cend) { mi = idx[eb + lane]; mr = rel[eb + lane]; }
                int t = 0;
                for (; t + 8 <= cend; t += 8) {
                    float2 v[8]; int rr[8];
                    #pragma unroll
                    for (int u = 0; u < 8; ++u) {
                        int s  = __shfl_sync(0xffffffffu, mi, t + u);
                        rr[u]  = __shfl_sync(0xffffffffu, mr, t + u);
                        v[u]   = *(const float2*)(xin + (size_t)s * 64 + 2 * lane);
                    }
                    #pragma unroll
                    for (int u = 0; u < 8; ++u) {
                        #pragma unroll
                        for (int r = 0; r < 8; ++r)
                            if (rr[u] == r) { acc[r].x += v[u].x; acc[r].y += v[u].y; }
                    }
                }
                for (; t < cend; ++t) {
                    int s = __shfl_sync(0xffffffffu, mi, t);
                    int r = __shfl_sync(0xffffffffu, mr, t);
                    float2 v = *(const float2*)(xin + (size_t)s * 64 + 2 * lane);
                    #pragma unroll
                    for (int rc = 0; rc < 8; ++rc)
                        if (r == rc) { acc[rc].x += v.x; acc[rc].y += v.y; }
                }
            }
            // store transposed: aggT[k][node]
            #pragma unroll
            for (int r = 0; r < 8; ++r) {
                int krow = r * 64 + 2 * lane;
                aggT[(size_t)krow * TNS + nl]       = acc[r].x;
                aggT[(size_t)(krow + 1) * TNS + nl] = acc[r].y;
            }
        }
    }
    __syncthreads();

    // ---- GEMM: K-split 8, thread tile 4 rows x CPG cols, FFMA2 -------------
    const int slot = ((warp & 1) << 5) | lane;   // 0..63 within k-slice
    const int ks   = warp >> 1;                  // 0..7 k-slice
    const int rg   = slot & 7;                   // row group (4 rows)
    const int cg   = slot >> 3;                  // col group (CPG cols)

    ull accp[2][CPAIR], accq[2][CPAIR];
    #pragma unroll
    for (int i = 0; i < 2; ++i)
        #pragma unroll
        for (int j = 0; j < CPAIR; ++j) { accp[i][j] = 0ull; accq[i][j] = 0ull; }
    float accs[4] = {0.f, 0.f, 0.f, 0.f};

    {
        const float* aT = aggT + (size_t)(ks * 64) * TNS + 4 * rg;
        const float* bT = wbuf + (size_t)(ks * 64) * F_OUT + CPG * cg;
        #pragma unroll 4
        for (int k = 0; k < 64; ++k) {
            ull a0 = *(const ull*)(aT);      // rows 4rg, 4rg+1
            ull a1 = *(const ull*)(aT + 2);  // rows 4rg+2, 4rg+3
            #pragma unroll
            for (int cp = 0; cp < CPAIR; ++cp) {
                float b0 = bT[2 * cp], b1 = bT[2 * cp + 1];
                ull pb = pk2(b0, b1), ps = pk2(b1, b0);
                ffma2(accp[0][cp], a0, pb);
                ffma2(accq[0][cp], a0, ps);
                ffma2(accp[1][cp], a1, pb);
                ffma2(accq[1][cp], a1, ps);
            }
            if (SCL) {
                float bs = bT[CPG - 1];
                float a0x, a0y, a1x, a1y;
                upk2(a0, a0x, a0y); upk2(a1, a1x, a1y);
                accs[0] = fmaf(a0x, bs, accs[0]);
                accs[1] = fmaf(a0y, bs, accs[1]);
                accs[2] = fmaf(a1x, bs, accs[2]);
                accs[3] = fmaf(a1y, bs, accs[3]);
            }
            aT += TNS; bT += F_OUT;
        }
    }
    __syncthreads();   // aggT reads complete; reuse region for partials

    // ---- write K-slice partials: red[ks][node][F_OUT] (overlays aggT) ------
    float* red = smem;
    {
        const int cb = CPG * cg;
        #pragma unroll
        for (int rp = 0; rp < 2; ++rp) {
            int r0 = 4 * rg + 2 * rp;
            float* R0 = red + (size_t)(ks * TN + r0) * F_OUT + cb;
            float* R1 = R0 + F_OUT;
            #pragma unroll
            for (int cp = 0; cp < CPAIR; ++cp) {
                float px, py, qx, qy;
                upk2(accp[rp][cp], px, py);
                upk2(accq[rp][cp], qx, qy);
                R0[2 * cp]     = px;   // [r0][c0]
                R1[2 * cp + 1] = py;   // [r1][c1]
                R0[2 * cp + 1] = qx;   // [r0][c1]
                R1[2 * cp]     = qy;   // [r1][c0]
            }
            if (SCL) {
                R0[CPG - 1] = accs[2 * rp];
                R1[CPG - 1] = accs[2 * rp + 1];
            }
        }
    }
    __syncthreads();

    // ---- reduce K-slices + epilogue -----------------------------------------
    if (FIRST) {
        // 512 threads = 32 nodes x 16 float4 groups
        int n  = tid >> 4;
        int fg = tid & 15;
        float4 s = make_float4(0.f, 0.f, 0.f, 0.f);
        #pragma unroll
        for (int k = 0; k < 8; ++k) {
            float4 v = *(const float4*)(red + (size_t)(k * TN + n) * 64 + 4 * fg);
            s.x += v.x; s.y += v.y; s.z += v.z; s.w += v.w;
        }
        int g = node0 + n;
        if (g < n_nodes) {
            s.x = fmaxf(s.x, 0.f); s.y = fmaxf(s.y, 0.f);
            s.z = fmaxf(s.z, 0.f); s.w = fmaxf(s.w, 0.f);
            *(float4*)(g_h + (size_t)g * 64 + 4 * fg) = s;
        }
    } else {
        // reduce into orow[32][40] (in wbuf region; W reads are done)
        float* orow = smem + AGGF;
        if (tid < TN * F_OUT / 4) {           // 320 threads
            int n  = tid / (F_OUT / 4);
            int fg = tid % (F_OUT / 4);
            float4 s = make_float4(0.f, 0.f, 0.f, 0.f);
            #pragma unroll
            for (int k = 0; k < 8; ++k) {
                float4 v = *(const float4*)(red + (size_t)(k * TN + n) * F_OUT + 4 * fg);
                s.x += v.x; s.y += v.y; s.z += v.z; s.w += v.w;
            }
            *(float4*)(orow + (size_t)n * F_OUT + 4 * fg) = s;
        }
        __syncthreads();
        // log-softmax: warp per node (2 nodes/warp)
        for (int nl = warp; nl < TN; nl += 16) {
            int g = node0 + nl;
            if (g >= n_nodes) continue;
            const float* row = orow + (size_t)nl * F_OUT;
            float v1 = row[lane];                                   // lane < 40
            float v2 = (lane + 32 < F_OUT) ? row[lane + 32] : -INFINITY;
            float m = fmaxf(v1, v2);
            #pragma unroll
            for (int o = 16; o; o >>= 1)
                m = fmaxf(m, __shfl_xor_sync(0xffffffffu, m, o));
            float s = expf(v1 - m) + ((lane + 32 < F_OUT) ? expf(v2 - m) : 0.f);
            #pragma unroll
            for (int o = 16; o; o >>= 1)
                s += __shfl_xor_sync(0xffffffffu, s, o);
            float lse = m + logf(s);
            out[(size_t)g * F_OUT + lane] = v1 - lse;
            if (lane + 32 < F_OUT)
                out[(size_t)g * F_OUT + lane + 32] = v2 - lse;
        }
    }
}

extern "C" void kernel_launch(void* const* d_in, const int* in_sizes, int n_in,
                              void* d_out, int out_size)
{
    const float* x   = (const float*)d_in[0];
    const int*   ptr = (const int*)  d_in[1];
    const int*   idx = (const int*)  d_in[2];
    const int*   rel = (const int*)  d_in[3];
    const float* W1  = (const float*)d_in[4];   // [8][64][64] -> [512][64]
    const float* W2  = (const float*)d_in[5];   // [8][64][40] -> [512][40]
    float* out = (float*)d_out;

    int n    = in_sizes[1] - 1;
    int grid = (n + 31) / 32;

    const int s1 = (512 * 34 + 512 * 64) * (int)sizeof(float);  // 200704 B
    const int s2 = (512 * 34 + 512 * 40) * (int)sizeof(float);  // 151552 B
    cudaFuncSetAttribute(rgcn_layer_kernel<64, true>,
                         cudaFuncAttributeMaxDynamicSharedMemorySize, s1);
    cudaFuncSetAttribute(rgcn_layer_kernel<40, false>,
                         cudaFuncAttributeMaxDynamicSharedMemorySize, s2);

    rgcn_layer_kernel<64, true ><<<grid, 512, s1>>>(x, ptr, idx, rel, W1, out, n);
    rgcn_layer_kernel<40, false><<<grid, 512, s2>>>(x, ptr, idx, rel, W2, out, n);
}